// round 14
// baseline (speedup 1.0000x reference)
#include <cuda_runtime.h>
#include <cuda_bf16.h>

#define M_TOK 4096
#define DM 64
#define NH 8
#define DFF_ 256
#define NL 4
#define ASPLIT 4

typedef unsigned long long ull;
typedef unsigned int u32;

// ---------------- scratch (device globals; no allocs allowed) ----------------
__device__ float g_x[M_TOK * DM];                 // fp32 residual stream
__device__ __nv_bfloat16 g_xb[M_TOK * DM];        // bf16 shadow of g_x
__device__ __nv_bfloat16 g_attnb[M_TOK * DM];     // attention output (bf16)
__device__ __nv_bfloat16 g_ffb[M_TOK * DFF_];     // FFN hidden (bf16)
__device__ __nv_bfloat16 g_qb[NH * M_TOK * 8];    // [h][m][8], pre-scaled
__device__ __nv_bfloat16 g_kb[NH * M_TOK * 8];    // [h][m][8]
__device__ __nv_bfloat16 g_vt[NH * 8 * M_TOK];    // [h][d][m]
__device__ __nv_bfloat16 g_ipwb[NL * 192 * 64];   // bf16 weights (prep kernel)
__device__ __nv_bfloat16 g_owb[NL * 64 * 64];
__device__ __nv_bfloat16 g_l1wb[NL * 256 * 64];
__device__ __nv_bfloat16 g_l2wb[NL * 64 * 256];
__device__ float g_pl2[ASPLIT * NH * M_TOK];      // attention l partials
__device__ float g_po[ASPLIT * NH * M_TOK * 8];   // attention o partials [sp][h][m][8]
__device__ float g_nx[M_TOK];
__device__ float g_ny[M_TOK];
__device__ float g_part[3 * 4096];

// ---------------- helpers ----------------------------------------------------
__device__ __forceinline__ ull ffma2(ull a, ull b, ull c) {
    ull d; asm("fma.rn.f32x2 %0, %1, %2, %3;" : "=l"(d) : "l"(a), "l"(b), "l"(c)); return d;
}
__device__ __forceinline__ ull pack2(float x, float y) {
    ull d; asm("mov.b64 %0, {%1, %2};" : "=l"(d) : "f"(x), "f"(y)); return d;
}
__device__ __forceinline__ float2 unpack2(ull d) {
    float2 f; asm("mov.b64 {%0, %1}, %2;" : "=f"(f.x), "=f"(f.y) : "l"(d)); return f;
}
__device__ __forceinline__ float ex2(float x) {
    float y; asm("ex2.approx.f32 %0, %1;" : "=f"(y) : "f"(x)); return y;
}
__device__ __forceinline__ float tf32r(float x) {
    u32 y; asm("cvt.rna.tf32.f32 %0, %1;" : "=r"(y) : "f"(x)); return __uint_as_float(y);
}
__device__ __forceinline__ u32 cvtpack(float hi, float lo) {
    u32 r; asm("cvt.rn.bf16x2.f32 %0, %1, %2;" : "=r"(r) : "f"(hi), "f"(lo)); return r;
}
__device__ __forceinline__ void mma_16x8x8(float& d0, float& d1, float& d2, float& d3,
                                           u32 a0, u32 a1, u32 b0) {
    asm("mma.sync.aligned.m16n8k8.row.col.f32.bf16.bf16.f32 "
        "{%0,%1,%2,%3},{%4,%5},{%6},{%7,%8,%9,%10};"
        : "=f"(d0), "=f"(d1), "=f"(d2), "=f"(d3)
        : "r"(a0), "r"(a1), "r"(b0), "f"(0.f), "f"(0.f), "f"(0.f), "f"(0.f));
}
__device__ __forceinline__ void mma_16x8x16(float& d0, float& d1, float& d2, float& d3,
                                            u32 a0, u32 a1, u32 a2, u32 a3, u32 b0, u32 b1) {
    asm("mma.sync.aligned.m16n8k16.row.col.f32.bf16.bf16.f32 "
        "{%0,%1,%2,%3},{%4,%5,%6,%7},{%8,%9},{%0,%1,%2,%3};"
        : "+f"(d0), "+f"(d1), "+f"(d2), "+f"(d3)
        : "r"(a0), "r"(a1), "r"(a2), "r"(a3), "r"(b0), "r"(b1));
}
__device__ __forceinline__ void mma_tf32(float& d0, float& d1, float& d2, float& d3,
                                         float a0, float a1, float a2, float a3,
                                         float b0, float b1) {
    asm("mma.sync.aligned.m16n8k8.row.col.f32.tf32.tf32.f32 "
        "{%0,%1,%2,%3},{%4,%5,%6,%7},{%8,%9},{%0,%1,%2,%3};"
        : "+f"(d0), "+f"(d1), "+f"(d2), "+f"(d3)
        : "r"(__float_as_uint(a0)), "r"(__float_as_uint(a1)),
          "r"(__float_as_uint(a2)), "r"(__float_as_uint(a3)),
          "r"(__float_as_uint(b0)), "r"(__float_as_uint(b1)));
}

#define QS (0.35355339059327373f * 1.4426950408889634f)

// ---------------- prep: convert all weights to bf16 --------------------------
__global__ void prep_weights(const float* __restrict__ ipw, const float* __restrict__ ow,
                             const float* __restrict__ l1w, const float* __restrict__ l2w) {
    int i = blockIdx.x * 256 + threadIdx.x;
    if (i < NL * 192 * 64) g_ipwb[i] = __float2bfloat16_rn(ipw[i]);
    else if (i < NL * (192 * 64 + 64 * 64)) {
        int j = i - NL * 192 * 64; g_owb[j] = __float2bfloat16_rn(ow[j]);
    } else if (i < NL * (192 * 64 + 64 * 64 + 256 * 64)) {
        int j = i - NL * (192 * 64 + 64 * 64); g_l1wb[j] = __float2bfloat16_rn(l1w[j]);
    } else {
        int j = i - NL * (192 * 64 + 64 * 64 + 256 * 64); g_l2wb[j] = __float2bfloat16_rn(l2w[j]);
    }
}

// ---------------- init: hsi -> g_x (fp32) + g_xb (bf16) ----------------------
__global__ void init_kernel(const float* __restrict__ hsi) {
    int i = (blockIdx.x * 128 + threadIdx.x) * 2;
    float2 v = *(const float2*)&hsi[i];
    *(float2*)&g_x[i] = v;
    *(u32*)&g_xb[i] = cvtpack(v.y, v.x);
}

// ------------- bf16 tile loader: 64 rows x 64 halves, [72]-pitch -------------
__device__ __forceinline__ void load_T64(__nv_bfloat16 (*Ts)[72], const __nv_bfloat16* P,
                                         int r0, int Kst, int k0, int tid) {
#pragma unroll
    for (int j = 0; j < 4; j++) {
        int i = tid + j * 128;
        int row = i >> 3, q = i & 7;
        *(uint4*)&Ts[row][q * 8] = *(const uint4*)(P + (size_t)(r0 + row) * Kst + k0 + q * 8);
    }
}

// ---------------- qkv GEMM: grid (3,64), block 128 ---------------------------
__global__ void gemm_qkv(const __nv_bfloat16* __restrict__ Wb, const float* __restrict__ bias) {
    __shared__ __nv_bfloat16 As[64][72], Ws[64][72];
    const int m0 = blockIdx.y * 64, sec = blockIdx.x;
    const int tid = threadIdx.x, lane = tid & 31;
    const int wm = (tid >> 5) * 16, r = lane >> 2, c = lane & 3;
    load_T64(As, g_xb, m0, 64, 0, tid);
    load_T64(Ws, Wb, sec * 64, 64, 0, tid);
    __syncthreads();
    float acc[8][4] = {};
#pragma unroll
    for (int ks = 0; ks < 4; ks++) {
        u32 a0 = *(const u32*)&As[wm + r][ks * 16 + 2 * c];
        u32 a1 = *(const u32*)&As[wm + r + 8][ks * 16 + 2 * c];
        u32 a2 = *(const u32*)&As[wm + r][ks * 16 + 2 * c + 8];
        u32 a3 = *(const u32*)&As[wm + r + 8][ks * 16 + 2 * c + 8];
#pragma unroll
        for (int s = 0; s < 8; s++) {
            u32 b0 = *(const u32*)&Ws[s * 8 + r][ks * 16 + 2 * c];
            u32 b1 = *(const u32*)&Ws[s * 8 + r][ks * 16 + 2 * c + 8];
            mma_16x8x16(acc[s][0], acc[s][1], acc[s][2], acc[s][3], a0, a1, a2, a3, b0, b1);
        }
    }
    const int row0 = m0 + wm + r, row1 = row0 + 8;
#pragma unroll
    for (int s = 0; s < 8; s++) {
        float2 bb = *(const float2*)&bias[sec * 64 + s * 8 + 2 * c];
        float v0 = acc[s][0] + bb.x, v1 = acc[s][1] + bb.y;
        float v2 = acc[s][2] + bb.x, v3 = acc[s][3] + bb.y;
        const int hh = s, dd = 2 * c;
        if (sec == 0) {
            *(u32*)&g_qb[((size_t)hh * M_TOK + row0) * 8 + dd] = cvtpack(v1 * QS, v0 * QS);
            *(u32*)&g_qb[((size_t)hh * M_TOK + row1) * 8 + dd] = cvtpack(v3 * QS, v2 * QS);
        } else if (sec == 1) {
            *(u32*)&g_kb[((size_t)hh * M_TOK + row0) * 8 + dd] = cvtpack(v1, v0);
            *(u32*)&g_kb[((size_t)hh * M_TOK + row1) * 8 + dd] = cvtpack(v3, v2);
        } else {
            g_vt[((size_t)hh * 8 + dd) * M_TOK + row0] = __float2bfloat16_rn(v0);
            g_vt[((size_t)hh * 8 + dd + 1) * M_TOK + row0] = __float2bfloat16_rn(v1);
            g_vt[((size_t)hh * 8 + dd) * M_TOK + row1] = __float2bfloat16_rn(v2);
            g_vt[((size_t)hh * 8 + dd + 1) * M_TOK + row1] = __float2bfloat16_rn(v3);
        }
    }
}

// ---------------- lin1 GEMM + relu: grid (4,64), block 128 -------------------
__global__ void gemm_ffn1(const __nv_bfloat16* __restrict__ Wb, const float* __restrict__ bias) {
    __shared__ __nv_bfloat16 As[64][72], Ws[64][72];
    const int n0 = blockIdx.x * 64, m0 = blockIdx.y * 64;
    const int tid = threadIdx.x, lane = tid & 31;
    const int wm = (tid >> 5) * 16, r = lane >> 2, c = lane & 3;
    load_T64(As, g_xb, m0, 64, 0, tid);
    load_T64(Ws, Wb, n0, 64, 0, tid);
    __syncthreads();
    float acc[8][4] = {};
#pragma unroll
    for (int ks = 0; ks < 4; ks++) {
        u32 a0 = *(const u32*)&As[wm + r][ks * 16 + 2 * c];
        u32 a1 = *(const u32*)&As[wm + r + 8][ks * 16 + 2 * c];
        u32 a2 = *(const u32*)&As[wm + r][ks * 16 + 2 * c + 8];
        u32 a3 = *(const u32*)&As[wm + r + 8][ks * 16 + 2 * c + 8];
#pragma unroll
        for (int s = 0; s < 8; s++) {
            u32 b0 = *(const u32*)&Ws[s * 8 + r][ks * 16 + 2 * c];
            u32 b1 = *(const u32*)&Ws[s * 8 + r][ks * 16 + 2 * c + 8];
            mma_16x8x16(acc[s][0], acc[s][1], acc[s][2], acc[s][3], a0, a1, a2, a3, b0, b1);
        }
    }
    const int row0 = m0 + wm + r, row1 = row0 + 8;
#pragma unroll
    for (int s = 0; s < 8; s++) {
        int col = n0 + s * 8 + 2 * c;
        float2 bb = *(const float2*)&bias[col];
        float v0 = fmaxf(acc[s][0] + bb.x, 0.f), v1 = fmaxf(acc[s][1] + bb.y, 0.f);
        float v2 = fmaxf(acc[s][2] + bb.x, 0.f), v3 = fmaxf(acc[s][3] + bb.y, 0.f);
        *(u32*)&g_ffb[(size_t)row0 * DFF_ + col] = cvtpack(v1, v0);
        *(u32*)&g_ffb[(size_t)row1 * DFF_ + col] = cvtpack(v3, v2);
    }
}

// -------- N=64 GEMM + residual + LayerNorm: grid 64, block 128 ---------------
__global__ void gemm_lnb(const __nv_bfloat16* __restrict__ Abf, int K,
                         const __nv_bfloat16* __restrict__ Wb, const float* __restrict__ bias,
                         const float* __restrict__ lnw, const float* __restrict__ lnb) {
    __shared__ __nv_bfloat16 As[64][72], Ws[64][72];
    const int m0 = blockIdx.x * 64;
    const int tid = threadIdx.x, lane = tid & 31;
    const int wm = (tid >> 5) * 16, r = lane >> 2, c = lane & 3;
    float acc[8][4] = {};
    for (int k0 = 0; k0 < K; k0 += 64) {
        load_T64(As, Abf, m0, K, k0, tid);
        load_T64(Ws, Wb, 0, K, k0, tid);
        __syncthreads();
#pragma unroll
        for (int ks = 0; ks < 4; ks++) {
            u32 a0 = *(const u32*)&As[wm + r][ks * 16 + 2 * c];
            u32 a1 = *(const u32*)&As[wm + r + 8][ks * 16 + 2 * c];
            u32 a2 = *(const u32*)&As[wm + r][ks * 16 + 2 * c + 8];
            u32 a3 = *(const u32*)&As[wm + r + 8][ks * 16 + 2 * c + 8];
#pragma unroll
            for (int s = 0; s < 8; s++) {
                u32 b0 = *(const u32*)&Ws[s * 8 + r][ks * 16 + 2 * c];
                u32 b1 = *(const u32*)&Ws[s * 8 + r][ks * 16 + 2 * c + 8];
                mma_16x8x16(acc[s][0], acc[s][1], acc[s][2], acc[s][3], a0, a1, a2, a3, b0, b1);
            }
        }
        __syncthreads();
    }
#pragma unroll
    for (int half = 0; half < 2; half++) {
        const int row = m0 + wm + r + half * 8;
        float rv[16];
        float sm = 0.f, sq = 0.f;
#pragma unroll
        for (int s = 0; s < 8; s++) {
            float2 res = *(const float2*)&g_x[row * 64 + s * 8 + 2 * c];
            float2 bb = *(const float2*)&bias[s * 8 + 2 * c];
            float x0 = res.x + acc[s][2 * half] + bb.x;
            float x1 = res.y + acc[s][2 * half + 1] + bb.y;
            rv[2 * s] = x0; rv[2 * s + 1] = x1;
            sm += x0 + x1; sq += x0 * x0 + x1 * x1;
        }
        sm += __shfl_xor_sync(0xffffffffu, sm, 1);
        sm += __shfl_xor_sync(0xffffffffu, sm, 2);
        sq += __shfl_xor_sync(0xffffffffu, sq, 1);
        sq += __shfl_xor_sync(0xffffffffu, sq, 2);
        float mu = sm * (1.0f / 64.0f);
        float var = sq * (1.0f / 64.0f) - mu * mu;
        float rstd = rsqrtf(var + 1e-5f);
#pragma unroll
        for (int s = 0; s < 8; s++) {
            float2 ww = *(const float2*)&lnw[s * 8 + 2 * c];
            float2 wb = *(const float2*)&lnb[s * 8 + 2 * c];
            float o0 = (rv[2 * s] - mu) * rstd * ww.x + wb.x;
            float o1 = (rv[2 * s + 1] - mu) * rstd * ww.y + wb.y;
            *(float2*)&g_x[row * 64 + s * 8 + 2 * c] = make_float2(o0, o1);
            *(u32*)&g_xb[row * 64 + s * 8 + 2 * c] = cvtpack(o1, o0);
        }
    }
}

// --------- split-K flash attention: grid (32, 8, ASPLIT), block 256 ----------
#define ATT_KT 256
__global__ void attn_kernel() {
    __shared__ __nv_bfloat16 Ks[ATT_KT][8];
    __shared__ __nv_bfloat16 Vt[8][ATT_KT + 8];
    const int h = blockIdx.y, sp = blockIdx.z;
    const int q0 = blockIdx.x * 128;
    const int tid = threadIdx.x, lane = tid & 31, w = tid >> 5;
    const int r = lane >> 2, cq = (lane & 3) * 2;
    const __nv_bfloat16* qh = g_qb + ((size_t)h * M_TOK + q0 + w * 16) * 8;
    u32 a0 = *(const u32*)(qh + r * 8 + cq);
    u32 a1 = *(const u32*)(qh + (r + 8) * 8 + cq);
    const ull C1p = pack2(0.6931471805599453f, 0.6931471805599453f);
    const ull C2p = pack2(0.2402265069591007f, 0.2402265069591007f);
    const ull ONEp = pack2(1.0f, 1.0f);
    const u32 ONESB = 0x3F803F80u;   // bf16x2 (1.0, 1.0)
    float o0 = 0, o1 = 0, o2 = 0, o3 = 0;
    float la0 = 0, la1 = 0, la2 = 0, la3 = 0;   // l via ones-mma (cols replicated)
    const int kstart = sp * (M_TOK / ASPLIT);
    for (int t0 = kstart; t0 < kstart + M_TOK / ASPLIT; t0 += ATT_KT) {
        ((float4*)Ks)[tid] = ((const float4*)(g_kb + ((size_t)h * M_TOK + t0) * 8))[tid];
        {
            int d = tid >> 5, col = (tid & 31) * 8;
            *(float4*)&Vt[d][col] = *(const float4*)(g_vt + ((size_t)h * 8 + d) * M_TOK + t0 + col);
        }
        __syncthreads();
#pragma unroll
        for (int kt = 0; kt < ATT_KT / 16; kt++) {
            const int kb = kt * 16;
            u32 b0 = *(const u32*)&Ks[kb + r][cq];
            u32 b1 = *(const u32*)&Ks[kb + 8 + r][cq];
            float d0, d1, d2, d3, d4, d5, d6, d7;
            mma_16x8x8(d0, d1, d2, d3, a0, a1, b0);
            mma_16x8x8(d4, d5, d6, d7, a0, a1, b1);
            ull t0p = pack2(d0, d2), t1p = pack2(d1, d3);
            ull t2p = pack2(d4, d6), t3p = pack2(d5, d7);
            ull e0 = ffma2(ffma2(C2p, t0p, C1p), t0p, ONEp);
            ull e1 = ffma2(ffma2(C2p, t1p, C1p), t1p, ONEp);
            ull e2 = ffma2(ffma2(C2p, t2p, C1p), t2p, ONEp);
            ull e3 = ffma2(ffma2(C2p, t3p, C1p), t3p, ONEp);
            float2 f0 = unpack2(e0), f1 = unpack2(e1), f2 = unpack2(e2), f3 = unpack2(e3);
            u32 p0 = cvtpack(f1.x, f0.x), p1 = cvtpack(f1.y, f0.y);
            u32 p2 = cvtpack(f3.x, f2.x), p3 = cvtpack(f3.y, f2.y);
            u32 vb0 = *(const u32*)&Vt[r][kb + cq];
            u32 vb1 = *(const u32*)&Vt[r][kb + 8 + cq];
            mma_16x8x16(o0, o1, o2, o3, p0, p1, p2, p3, vb0, vb1);
            mma_16x8x16(la0, la1, la2, la3, p0, p1, p2, p3, ONESB, ONESB);
        }
        __syncthreads();
    }
    // partials: o (unnormalized) and l; l replicated across columns -> c==0 writes
    float* po = g_po + (((size_t)sp * NH + h) * M_TOK) * 8;
    *(float2*)&po[(size_t)(q0 + w * 16 + r) * 8 + cq] = make_float2(o0, o1);
    *(float2*)&po[(size_t)(q0 + w * 16 + r + 8) * 8 + cq] = make_float2(o2, o3);
    if ((lane & 3) == 0) {
        g_pl2[(sp * NH + h) * M_TOK + q0 + w * 16 + r] = la0;
        g_pl2[(sp * NH + h) * M_TOK + q0 + w * 16 + r + 8] = la2;
    }
}

// ---------------- combine split-K partials -> g_attnb (bf16) -----------------
__global__ void attn_combine() {
    const int idx = blockIdx.x * 256 + threadIdx.x;  // 0..32767
    const int h = idx >> 12, m = idx & 4095;
    float l = 0.0f;
    float4 s0 = make_float4(0.f, 0.f, 0.f, 0.f), s1 = make_float4(0.f, 0.f, 0.f, 0.f);
#pragma unroll
    for (int sp = 0; sp < ASPLIT; sp++) {
        l += g_pl2[(sp * NH + h) * M_TOK + m];
        const float4* p = (const float4*)&g_po[(((size_t)sp * NH + h) * M_TOK + m) * 8];
        float4 x0 = p[0], x1 = p[1];
        s0.x += x0.x; s0.y += x0.y; s0.z += x0.z; s0.w += x0.w;
        s1.x += x1.x; s1.y += x1.y; s1.z += x1.z; s1.w += x1.w;
    }
    float inv = 1.0f / l;
    u32 w0 = cvtpack(s0.y * inv, s0.x * inv);
    u32 w1 = cvtpack(s0.w * inv, s0.z * inv);
    u32 w2 = cvtpack(s1.y * inv, s1.x * inv);
    u32 w3 = cvtpack(s1.w * inv, s1.z * inv);
    *(uint4*)&g_attnb[(size_t)m * DM + h * 8] = make_uint4(w0, w1, w2, w3);
}

// ------------- fused prune + output + row norms (x and rgb) ------------------
__global__ void prune_norms(const float* __restrict__ mask, float* __restrict__ out,
                            const float* __restrict__ rgb) {
    const int rid = blockIdx.x * 8 + (threadIdx.x >> 5);   // 0..8191
    const int lane = threadIdx.x & 31;
    if (rid < M_TOK) {
        float m0 = mask[lane], m1 = mask[lane + 32];
        float a = g_x[rid * DM + lane] * m0;
        float b = g_x[rid * DM + lane + 32] * m1;
        g_x[rid * DM + lane] = a; g_x[rid * DM + lane + 32] = b;
        out[rid * DM + lane] = a; out[rid * DM + lane + 32] = b;
        float sq = a * a + b * b;
#pragma unroll
        for (int o = 16; o; o >>= 1) sq += __shfl_xor_sync(0xffffffffu, sq, o);
        if (lane == 0) g_nx[rid] = sq;
    } else {
        const float* src = rgb + (size_t)(rid - M_TOK) * DM;
        float a = src[lane], b = src[lane + 32];
        float sq = a * a + b * b;
#pragma unroll
        for (int o = 16; o; o >>= 1) sq += __shfl_xor_sync(0xffffffffu, sq, o);
        if (lane == 0) g_ny[rid - M_TOK] = sq;
    }
}

// ---------------- MMD: tf32 tensor-core pairwise Gaussian sums ---------------
__global__ void mmd_kernel(const float* __restrict__ rgb) {
    __shared__ float As[64][68];
    __shared__ float Bs[64][68];
    __shared__ float nA[64], nB[64];
    __shared__ float red[256];
    const int z = blockIdx.z;
    const int bx = blockIdx.x, by = blockIdx.y;
    const int tid = threadIdx.x;
    if (z < 2 && bx < by) {
        if (tid == 0) g_part[z * 4096 + by * 64 + bx] = 0.0f;
        return;
    }
    const float* A = (z == 1) ? rgb : g_x;
    const float* B = (z == 0) ? g_x : rgb;
    const float* nAp = (z == 1) ? g_ny : g_nx;
    const float* nBp = (z == 0) ? g_nx : g_ny;
    const int m0 = by * 64, n0 = bx * 64;
#pragma unroll
    for (int i = 0; i < 4; i++) {
        int fidx = tid + i * 256;
        int rr = fidx >> 4, c4 = fidx & 15;
        float4 va = *(const float4*)&A[(size_t)(m0 + rr) * DM + c4 * 4];
        float4 vb = *(const float4*)&B[(size_t)(n0 + rr) * DM + c4 * 4];
        As[c4 * 4 + 0][rr] = tf32r(va.x); As[c4 * 4 + 1][rr] = tf32r(va.y);
        As[c4 * 4 + 2][rr] = tf32r(va.z); As[c4 * 4 + 3][rr] = tf32r(va.w);
        Bs[c4 * 4 + 0][rr] = tf32r(vb.x); Bs[c4 * 4 + 1][rr] = tf32r(vb.y);
        Bs[c4 * 4 + 2][rr] = tf32r(vb.z); Bs[c4 * 4 + 3][rr] = tf32r(vb.w);
    }
    if (tid < 64) { nA[tid] = nAp[m0 + tid]; nB[tid] = nBp[n0 + tid]; }
    __syncthreads();
    const int w = tid >> 5, lane = tid & 31;
    const int wm = (w >> 1) * 16, wn = (w & 1) * 32;
    const int r = lane >> 2, c = lane & 3;
    float a[8][4];
#pragma unroll
    for (int ks = 0; ks < 8; ks++) {
        a[ks][0] = As[ks * 8 + c][wm + r];
        a[ks][1] = As[ks * 8 + c][wm + r + 8];
        a[ks][2] = As[ks * 8 + c + 4][wm + r];
        a[ks][3] = As[ks * 8 + c + 4][wm + r + 8];
    }
    float acc[4][4] = {};
#pragma unroll
    for (int ks = 0; ks < 8; ks++) {
#pragma unroll
        for (int s = 0; s < 4; s++) {
            float b0 = Bs[ks * 8 + c][wn + s * 8 + r];
            float b1 = Bs[ks * 8 + c + 4][wn + s * 8 + r];
            mma_tf32(acc[s][0], acc[s][1], acc[s][2], acc[s][3],
                     a[ks][0], a[ks][1], a[ks][2], a[ks][3], b0, b1);
        }
    }
    const float c2 = -0.5f * 1.4426950408889634f;
    const float na0 = nA[wm + r], na1 = nA[wm + r + 8];
    float sum = 0.0f;
#pragma unroll
    for (int s = 0; s < 4; s++) {
        float nb0 = nB[wn + s * 8 + 2 * c], nb1 = nB[wn + s * 8 + 2 * c + 1];
        sum += ex2(c2 * (na0 + nb0 - 2.0f * acc[s][0]));
        sum += ex2(c2 * (na0 + nb1 - 2.0f * acc[s][1]));
        sum += ex2(c2 * (na1 + nb0 - 2.0f * acc[s][2]));
        sum += ex2(c2 * (na1 + nb1 - 2.0f * acc[s][3]));
    }
    if (z < 2 && bx != by) sum *= 2.0f;
    red[tid] = sum;
    __syncthreads();
#pragma unroll
    for (int s = 128; s; s >>= 1) {
        if (tid < s) red[tid] += red[tid + s];
        __syncthreads();
    }
    if (tid == 0) g_part[z * 4096 + by * 64 + bx] = red[0];
}

__global__ void mmd_final(float* __restrict__ out) {
    __shared__ float red[256];
    const int tid = threadIdx.x;
    float s[3];
    for (int z = 0; z < 3; z++) {
        float acc = 0.0f;
        for (int i = tid; i < 4096; i += 256) acc += g_part[z * 4096 + i];
        red[tid] = acc;
        __syncthreads();
#pragma unroll
        for (int st = 128; st; st >>= 1) {
            if (tid < st) red[tid] += red[tid + st];
            __syncthreads();
        }
        s[z] = red[0];
        __syncthreads();
    }
    if (tid == 0) {
        const float inv = 1.0f / (4096.0f * 4096.0f);
        out[M_TOK * DM] = (s[0] + s[1] - 2.0f * s[2]) * inv;
    }
}

// ---------------- host orchestration ----------------------------------------
extern "C" void kernel_launch(void* const* d_in, const int* in_sizes, int n_in,
                              void* d_out, int out_size) {
    (void)in_sizes; (void)n_in; (void)out_size;
    const float* hsi  = (const float*)d_in[0];
    const float* rgb  = (const float*)d_in[1];
    const float* ipw  = (const float*)d_in[2];
    const float* ipb  = (const float*)d_in[3];
    const float* ow   = (const float*)d_in[4];
    const float* ob   = (const float*)d_in[5];
    const float* l1w  = (const float*)d_in[6];
    const float* l1b  = (const float*)d_in[7];
    const float* l2w  = (const float*)d_in[8];
    const float* l2b  = (const float*)d_in[9];
    const float* n1w  = (const float*)d_in[10];
    const float* n1b  = (const float*)d_in[11];
    const float* n2w  = (const float*)d_in[12];
    const float* n2b  = (const float*)d_in[13];
    const float* mask = (const float*)d_in[14];
    float* out = (float*)d_out;

    __nv_bfloat16 *pipwb, *powb, *pl1wb, *pl2wb, *pattnb, *pffb;
    cudaGetSymbolAddress((void**)&pipwb, g_ipwb);
    cudaGetSymbolAddress((void**)&powb, g_owb);
    cudaGetSymbolAddress((void**)&pl1wb, g_l1wb);
    cudaGetSymbolAddress((void**)&pl2wb, g_l2wb);
    cudaGetSymbolAddress((void**)&pattnb, g_attnb);
    cudaGetSymbolAddress((void**)&pffb, g_ffb);

    prep_weights<<<768, 256>>>(ipw, ow, l1w, l2w);
    init_kernel<<<1024, 128>>>(hsi);

    for (int l = 0; l < NL; l++) {
        gemm_qkv<<<dim3(3, 64), 128>>>(pipwb + (size_t)l * 192 * 64, ipb + l * 192);
        attn_kernel<<<dim3(M_TOK / 128, NH, ASPLIT), 256>>>();
        attn_combine<<<128, 256>>>();
        gemm_lnb<<<64, 128>>>(pattnb, 64, powb + (size_t)l * 64 * 64, ob + l * 64,
                              n1w + l * 64, n1b + l * 64);
        gemm_ffn1<<<dim3(4, 64), 128>>>(pl1wb + (size_t)l * 256 * 64, l1b + l * 256);
        gemm_lnb<<<64, 128>>>(pffb, 256, pl2wb + (size_t)l * 64 * 256, l2b + l * 64,
                              n2w + l * 64, n2b + l * 64);
    }
    prune_norms<<<1024, 256>>>(mask, out, rgb);
    mmd_kernel<<<dim3(64, 64, 3), 256>>>(rgb);
    mmd_final<<<1, 256>>>(out);
}

// round 15
// speedup vs baseline: 1.4792x; 1.4792x over previous
#include <cuda_runtime.h>
#include <cuda_bf16.h>

#define M_TOK 4096
#define DM 64
#define NH 8
#define DFF_ 256
#define NL 4
#define ASPLIT 2

typedef unsigned long long ull;
typedef unsigned int u32;

// ---------------- scratch (device globals; no allocs allowed) ----------------
__device__ float g_x[M_TOK * DM];                 // fp32 residual stream
__device__ __nv_bfloat16 g_xb[M_TOK * DM];        // bf16 shadow of g_x
__device__ __nv_bfloat16 g_attnb[M_TOK * DM];     // attention output (bf16)
__device__ __nv_bfloat16 g_ffb[M_TOK * DFF_];     // FFN hidden (bf16)
__device__ __nv_bfloat16 g_qb[NH * M_TOK * 8];    // [h][m][8], pre-scaled
__device__ __nv_bfloat16 g_kb[NH * M_TOK * 8];    // [h][m][8]
__device__ __nv_bfloat16 g_vt[NH * 8 * M_TOK];    // [h][d][m]
__device__ __nv_bfloat16 g_ipwb[NL * 192 * 64];   // bf16 weights (prep kernel)
__device__ __nv_bfloat16 g_owb[NL * 64 * 64];
__device__ __nv_bfloat16 g_l1wb[NL * 256 * 64];
__device__ __nv_bfloat16 g_l2wb[NL * 64 * 256];
__device__ float g_pl2[ASPLIT * NH * M_TOK];      // attention l partials
__device__ float g_po[ASPLIT * NH * M_TOK * 8];   // attention o partials [sp][h][m][8]
__device__ float g_nx[M_TOK];
__device__ float g_ny[M_TOK];
__device__ float g_part[3 * 4096];

// ---------------- helpers ----------------------------------------------------
__device__ __forceinline__ ull ffma2(ull a, ull b, ull c) {
    ull d; asm("fma.rn.f32x2 %0, %1, %2, %3;" : "=l"(d) : "l"(a), "l"(b), "l"(c)); return d;
}
__device__ __forceinline__ ull pack2(float x, float y) {
    ull d; asm("mov.b64 %0, {%1, %2};" : "=l"(d) : "f"(x), "f"(y)); return d;
}
__device__ __forceinline__ float2 unpack2(ull d) {
    float2 f; asm("mov.b64 {%0, %1}, %2;" : "=f"(f.x), "=f"(f.y) : "l"(d)); return f;
}
__device__ __forceinline__ float ex2(float x) {
    float y; asm("ex2.approx.f32 %0, %1;" : "=f"(y) : "f"(x)); return y;
}
__device__ __forceinline__ float tf32r(float x) {
    u32 y; asm("cvt.rna.tf32.f32 %0, %1;" : "=r"(y) : "f"(x)); return __uint_as_float(y);
}
__device__ __forceinline__ u32 cvtpack(float hi, float lo) {
    u32 r; asm("cvt.rn.bf16x2.f32 %0, %1, %2;" : "=r"(r) : "f"(hi), "f"(lo)); return r;
}
__device__ __forceinline__ void mma_16x8x8(float& d0, float& d1, float& d2, float& d3,
                                           u32 a0, u32 a1, u32 b0) {
    asm("mma.sync.aligned.m16n8k8.row.col.f32.bf16.bf16.f32 "
        "{%0,%1,%2,%3},{%4,%5},{%6},{%7,%8,%9,%10};"
        : "=f"(d0), "=f"(d1), "=f"(d2), "=f"(d3)
        : "r"(a0), "r"(a1), "r"(b0), "f"(0.f), "f"(0.f), "f"(0.f), "f"(0.f));
}
__device__ __forceinline__ void mma_16x8x16(float& d0, float& d1, float& d2, float& d3,
                                            u32 a0, u32 a1, u32 a2, u32 a3, u32 b0, u32 b1) {
    asm("mma.sync.aligned.m16n8k16.row.col.f32.bf16.bf16.f32 "
        "{%0,%1,%2,%3},{%4,%5,%6,%7},{%8,%9},{%0,%1,%2,%3};"
        : "+f"(d0), "+f"(d1), "+f"(d2), "+f"(d3)
        : "r"(a0), "r"(a1), "r"(a2), "r"(a3), "r"(b0), "r"(b1));
}
__device__ __forceinline__ void mma_tf32(float& d0, float& d1, float& d2, float& d3,
                                         float a0, float a1, float a2, float a3,
                                         float b0, float b1) {
    asm("mma.sync.aligned.m16n8k8.row.col.f32.tf32.tf32.f32 "
        "{%0,%1,%2,%3},{%4,%5,%6,%7},{%8,%9},{%0,%1,%2,%3};"
        : "+f"(d0), "+f"(d1), "+f"(d2), "+f"(d3)
        : "r"(__float_as_uint(a0)), "r"(__float_as_uint(a1)),
          "r"(__float_as_uint(a2)), "r"(__float_as_uint(a3)),
          "r"(__float_as_uint(b0)), "r"(__float_as_uint(b1)));
}

#define QS (0.35355339059327373f * 1.4426950408889634f)

// ---------------- prep: convert all weights to bf16 --------------------------
__global__ void prep_weights(const float* __restrict__ ipw, const float* __restrict__ ow,
                             const float* __restrict__ l1w, const float* __restrict__ l2w) {
    int i = blockIdx.x * 256 + threadIdx.x;
    if (i < NL * 192 * 64) g_ipwb[i] = __float2bfloat16_rn(ipw[i]);
    else if (i < NL * (192 * 64 + 64 * 64)) {
        int j = i - NL * 192 * 64; g_owb[j] = __float2bfloat16_rn(ow[j]);
    } else if (i < NL * (192 * 64 + 64 * 64 + 256 * 64)) {
        int j = i - NL * (192 * 64 + 64 * 64); g_l1wb[j] = __float2bfloat16_rn(l1w[j]);
    } else {
        int j = i - NL * (192 * 64 + 64 * 64 + 256 * 64); g_l2wb[j] = __float2bfloat16_rn(l2w[j]);
    }
}

// ---------------- init: hsi -> g_x (fp32) + g_xb (bf16) ----------------------
__global__ void init_kernel(const float* __restrict__ hsi) {
    int i = (blockIdx.x * 128 + threadIdx.x) * 2;
    float2 v = *(const float2*)&hsi[i];
    *(float2*)&g_x[i] = v;
    *(u32*)&g_xb[i] = cvtpack(v.y, v.x);
}

// ------- bf16 tile loader (256 threads): 64 rows x 64 halves, [72]-pitch -----
__device__ __forceinline__ void load_T64_256(__nv_bfloat16 (*Ts)[72], const __nv_bfloat16* P,
                                             int r0, int Kst, int k0, int tid) {
#pragma unroll
    for (int j = 0; j < 2; j++) {
        int i = tid + j * 256;
        int row = i >> 3, q = i & 7;
        *(uint4*)&Ts[row][q * 8] = *(const uint4*)(P + (size_t)(r0 + row) * Kst + k0 + q * 8);
    }
}

// ------ shared 64x64 mma: 8 warps, warp tile 16 rows x 32 cols ---------------
__device__ __forceinline__ void mma_64x64(const __nv_bfloat16 (*As)[72],
                                          const __nv_bfloat16 (*Ws)[72],
                                          int wm, int wn, int r, int c, float acc[4][4]) {
#pragma unroll
    for (int ks = 0; ks < 4; ks++) {
        u32 a0 = *(const u32*)&As[wm + r][ks * 16 + 2 * c];
        u32 a1 = *(const u32*)&As[wm + r + 8][ks * 16 + 2 * c];
        u32 a2 = *(const u32*)&As[wm + r][ks * 16 + 2 * c + 8];
        u32 a3 = *(const u32*)&As[wm + r + 8][ks * 16 + 2 * c + 8];
#pragma unroll
        for (int s = 0; s < 4; s++) {
            u32 b0 = *(const u32*)&Ws[wn + s * 8 + r][ks * 16 + 2 * c];
            u32 b1 = *(const u32*)&Ws[wn + s * 8 + r][ks * 16 + 2 * c + 8];
            mma_16x8x16(acc[s][0], acc[s][1], acc[s][2], acc[s][3], a0, a1, a2, a3, b0, b1);
        }
    }
}

// ---------------- qkv GEMM: grid (3,64), block 256 ---------------------------
__global__ void gemm_qkv(const __nv_bfloat16* __restrict__ Wb, const float* __restrict__ bias) {
    __shared__ __nv_bfloat16 As[64][72], Ws[64][72];
    const int m0 = blockIdx.y * 64, sec = blockIdx.x;
    const int tid = threadIdx.x, lane = tid & 31, w = tid >> 5;
    const int wm = (w >> 1) * 16, wn = (w & 1) * 32;
    const int r = lane >> 2, c = lane & 3;
    load_T64_256(As, g_xb, m0, 64, 0, tid);
    load_T64_256(Ws, Wb, sec * 64, 64, 0, tid);
    __syncthreads();
    float acc[4][4] = {};
    mma_64x64(As, Ws, wm, wn, r, c, acc);
    const int row0 = m0 + wm + r, row1 = row0 + 8;
#pragma unroll
    for (int s = 0; s < 4; s++) {
        int col = wn + s * 8 + 2 * c;
        float2 bb = *(const float2*)&bias[sec * 64 + col];
        float v0 = acc[s][0] + bb.x, v1 = acc[s][1] + bb.y;
        float v2 = acc[s][2] + bb.x, v3 = acc[s][3] + bb.y;
        const int hh = (w & 1) * 4 + s, dd = 2 * c;
        if (sec == 0) {
            *(u32*)&g_qb[((size_t)hh * M_TOK + row0) * 8 + dd] = cvtpack(v1 * QS, v0 * QS);
            *(u32*)&g_qb[((size_t)hh * M_TOK + row1) * 8 + dd] = cvtpack(v3 * QS, v2 * QS);
        } else if (sec == 1) {
            *(u32*)&g_kb[((size_t)hh * M_TOK + row0) * 8 + dd] = cvtpack(v1, v0);
            *(u32*)&g_kb[((size_t)hh * M_TOK + row1) * 8 + dd] = cvtpack(v3, v2);
        } else {
            g_vt[((size_t)hh * 8 + dd) * M_TOK + row0] = __float2bfloat16_rn(v0);
            g_vt[((size_t)hh * 8 + dd + 1) * M_TOK + row0] = __float2bfloat16_rn(v1);
            g_vt[((size_t)hh * 8 + dd) * M_TOK + row1] = __float2bfloat16_rn(v2);
            g_vt[((size_t)hh * 8 + dd + 1) * M_TOK + row1] = __float2bfloat16_rn(v3);
        }
    }
}

// ---------------- lin1 GEMM + relu: grid (4,64), block 256 -------------------
__global__ void gemm_ffn1(const __nv_bfloat16* __restrict__ Wb, const float* __restrict__ bias) {
    __shared__ __nv_bfloat16 As[64][72], Ws[64][72];
    const int n0 = blockIdx.x * 64, m0 = blockIdx.y * 64;
    const int tid = threadIdx.x, lane = tid & 31, w = tid >> 5;
    const int wm = (w >> 1) * 16, wn = (w & 1) * 32;
    const int r = lane >> 2, c = lane & 3;
    load_T64_256(As, g_xb, m0, 64, 0, tid);
    load_T64_256(Ws, Wb, n0, 64, 0, tid);
    __syncthreads();
    float acc[4][4] = {};
    mma_64x64(As, Ws, wm, wn, r, c, acc);
    const int row0 = m0 + wm + r, row1 = row0 + 8;
#pragma unroll
    for (int s = 0; s < 4; s++) {
        int col = n0 + wn + s * 8 + 2 * c;
        float2 bb = *(const float2*)&bias[col];
        float v0 = fmaxf(acc[s][0] + bb.x, 0.f), v1 = fmaxf(acc[s][1] + bb.y, 0.f);
        float v2 = fmaxf(acc[s][2] + bb.x, 0.f), v3 = fmaxf(acc[s][3] + bb.y, 0.f);
        *(u32*)&g_ffb[(size_t)row0 * DFF_ + col] = cvtpack(v1, v0);
        *(u32*)&g_ffb[(size_t)row1 * DFF_ + col] = cvtpack(v3, v2);
    }
}

// -------- N=64 GEMM + residual + LayerNorm: grid 64, block 256 ---------------
__global__ void gemm_lnb(const __nv_bfloat16* __restrict__ Abf, int K,
                         const __nv_bfloat16* __restrict__ Wb, const float* __restrict__ bias,
                         const float* __restrict__ lnw, const float* __restrict__ lnb) {
    __shared__ __nv_bfloat16 As[64][72], Ws[64][72];
    __shared__ float sws[8][16], sqs[8][16];
    const int m0 = blockIdx.x * 64;
    const int tid = threadIdx.x, lane = tid & 31, w = tid >> 5;
    const int wm = (w >> 1) * 16, wn = (w & 1) * 32;
    const int r = lane >> 2, c = lane & 3;
    float acc[4][4] = {};
    for (int k0 = 0; k0 < K; k0 += 64) {
        load_T64_256(As, Abf, m0, K, k0, tid);
        load_T64_256(Ws, Wb, 0, K, k0, tid);
        __syncthreads();
        mma_64x64(As, Ws, wm, wn, r, c, acc);
        __syncthreads();
    }
    const int row0 = m0 + wm + r, row1 = row0 + 8;
    // x = resid + gemm + bias for this warp's 32 cols of rows row0/row1
    float rv[4][4];
    float sm0 = 0.f, sq0 = 0.f, sm1 = 0.f, sq1 = 0.f;
#pragma unroll
    for (int s = 0; s < 4; s++) {
        int col = wn + s * 8 + 2 * c;
        float2 bb = *(const float2*)&bias[col];
        float2 re0 = *(const float2*)&g_x[row0 * 64 + col];
        float2 re1 = *(const float2*)&g_x[row1 * 64 + col];
        rv[s][0] = re0.x + acc[s][0] + bb.x;
        rv[s][1] = re0.y + acc[s][1] + bb.y;
        rv[s][2] = re1.x + acc[s][2] + bb.x;
        rv[s][3] = re1.y + acc[s][3] + bb.y;
        sm0 += rv[s][0] + rv[s][1]; sq0 += rv[s][0] * rv[s][0] + rv[s][1] * rv[s][1];
        sm1 += rv[s][2] + rv[s][3]; sq1 += rv[s][2] * rv[s][2] + rv[s][3] * rv[s][3];
    }
    sm0 += __shfl_xor_sync(0xffffffffu, sm0, 1); sm0 += __shfl_xor_sync(0xffffffffu, sm0, 2);
    sq0 += __shfl_xor_sync(0xffffffffu, sq0, 1); sq0 += __shfl_xor_sync(0xffffffffu, sq0, 2);
    sm1 += __shfl_xor_sync(0xffffffffu, sm1, 1); sm1 += __shfl_xor_sync(0xffffffffu, sm1, 2);
    sq1 += __shfl_xor_sync(0xffffffffu, sq1, 1); sq1 += __shfl_xor_sync(0xffffffffu, sq1, 2);
    if (c == 0) {
        sws[w][r] = sm0; sqs[w][r] = sq0;
        sws[w][r + 8] = sm1; sqs[w][r + 8] = sq1;
    }
    __syncthreads();
    const int wp = w ^ 1;   // partner warp covering the other 32 cols of same rows
    float tm0 = sws[w][r] + sws[wp][r], tq0 = sqs[w][r] + sqs[wp][r];
    float tm1 = sws[w][r + 8] + sws[wp][r + 8], tq1 = sqs[w][r + 8] + sqs[wp][r + 8];
    float mu0 = tm0 * (1.0f / 64.0f), mu1 = tm1 * (1.0f / 64.0f);
    float rs0 = rsqrtf(tq0 * (1.0f / 64.0f) - mu0 * mu0 + 1e-5f);
    float rs1 = rsqrtf(tq1 * (1.0f / 64.0f) - mu1 * mu1 + 1e-5f);
#pragma unroll
    for (int s = 0; s < 4; s++) {
        int col = wn + s * 8 + 2 * c;
        float2 ww = *(const float2*)&lnw[col];
        float2 wb = *(const float2*)&lnb[col];
        float y0 = (rv[s][0] - mu0) * rs0 * ww.x + wb.x;
        float y1 = (rv[s][1] - mu0) * rs0 * ww.y + wb.y;
        float y2 = (rv[s][2] - mu1) * rs1 * ww.x + wb.x;
        float y3 = (rv[s][3] - mu1) * rs1 * ww.y + wb.y;
        *(float2*)&g_x[row0 * 64 + col] = make_float2(y0, y1);
        *(float2*)&g_x[row1 * 64 + col] = make_float2(y2, y3);
        *(u32*)&g_xb[row0 * 64 + col] = cvtpack(y1, y0);
        *(u32*)&g_xb[row1 * 64 + col] = cvtpack(y3, y2);
    }
}

// --------- split-K flash attention: grid (32, 8, ASPLIT), block 256 ----------
#define ATT_KT 256
__global__ void attn_kernel() {
    __shared__ __nv_bfloat16 Ks[ATT_KT][8];
    __shared__ __nv_bfloat16 Vt[8][ATT_KT + 8];
    const int h = blockIdx.y, sp = blockIdx.z;
    const int q0 = blockIdx.x * 128;
    const int tid = threadIdx.x, lane = tid & 31, w = tid >> 5;
    const int r = lane >> 2, cq = (lane & 3) * 2;
    const __nv_bfloat16* qh = g_qb + ((size_t)h * M_TOK + q0 + w * 16) * 8;
    u32 a0 = *(const u32*)(qh + r * 8 + cq);
    u32 a1 = *(const u32*)(qh + (r + 8) * 8 + cq);
    const ull C1p = pack2(0.6931471805599453f, 0.6931471805599453f);
    const ull C2p = pack2(0.2402265069591007f, 0.2402265069591007f);
    const ull ONEp = pack2(1.0f, 1.0f);
    const u32 ONESB = 0x3F803F80u;   // bf16x2 (1.0, 1.0)
    float o0 = 0, o1 = 0, o2 = 0, o3 = 0;
    float la0 = 0, la1 = 0, la2 = 0, la3 = 0;   // l via ones-mma (cols replicated)
    const int kstart = sp * (M_TOK / ASPLIT);
    for (int t0 = kstart; t0 < kstart + M_TOK / ASPLIT; t0 += ATT_KT) {
        ((float4*)Ks)[tid] = ((const float4*)(g_kb + ((size_t)h * M_TOK + t0) * 8))[tid];
        {
            int d = tid >> 5, col = (tid & 31) * 8;
            *(float4*)&Vt[d][col] = *(const float4*)(g_vt + ((size_t)h * 8 + d) * M_TOK + t0 + col);
        }
        __syncthreads();
#pragma unroll 4
        for (int kt = 0; kt < ATT_KT / 16; kt++) {
            const int kb = kt * 16;
            u32 b0 = *(const u32*)&Ks[kb + r][cq];
            u32 b1 = *(const u32*)&Ks[kb + 8 + r][cq];
            float d0, d1, d2, d3, d4, d5, d6, d7;
            mma_16x8x8(d0, d1, d2, d3, a0, a1, b0);
            mma_16x8x8(d4, d5, d6, d7, a0, a1, b1);
            ull t0p = pack2(d0, d2), t1p = pack2(d1, d3);
            ull t2p = pack2(d4, d6), t3p = pack2(d5, d7);
            ull e0 = ffma2(ffma2(C2p, t0p, C1p), t0p, ONEp);
            ull e1 = ffma2(ffma2(C2p, t1p, C1p), t1p, ONEp);
            ull e2 = ffma2(ffma2(C2p, t2p, C1p), t2p, ONEp);
            ull e3 = ffma2(ffma2(C2p, t3p, C1p), t3p, ONEp);
            float2 f0 = unpack2(e0), f1 = unpack2(e1), f2 = unpack2(e2), f3 = unpack2(e3);
            u32 p0 = cvtpack(f1.x, f0.x), p1 = cvtpack(f1.y, f0.y);
            u32 p2 = cvtpack(f3.x, f2.x), p3 = cvtpack(f3.y, f2.y);
            u32 vb0 = *(const u32*)&Vt[r][kb + cq];
            u32 vb1 = *(const u32*)&Vt[r][kb + 8 + cq];
            mma_16x8x16(o0, o1, o2, o3, p0, p1, p2, p3, vb0, vb1);
            mma_16x8x16(la0, la1, la2, la3, p0, p1, p2, p3, ONESB, ONESB);
        }
        __syncthreads();
    }
    // partials: o (unnormalized) and l; l replicated across columns -> c==0 writes
    float* po = g_po + (((size_t)sp * NH + h) * M_TOK) * 8;
    *(float2*)&po[(size_t)(q0 + w * 16 + r) * 8 + cq] = make_float2(o0, o1);
    *(float2*)&po[(size_t)(q0 + w * 16 + r + 8) * 8 + cq] = make_float2(o2, o3);
    if ((lane & 3) == 0) {
        g_pl2[(sp * NH + h) * M_TOK + q0 + w * 16 + r] = la0;
        g_pl2[(sp * NH + h) * M_TOK + q0 + w * 16 + r + 8] = la2;
    }
}

// ---------------- combine split-K partials -> g_attnb (bf16) -----------------
__global__ void attn_combine() {
    const int idx = blockIdx.x * 256 + threadIdx.x;  // 0..32767
    const int h = idx >> 12, m = idx & 4095;
    float l = 0.0f;
    float4 s0 = make_float4(0.f, 0.f, 0.f, 0.f), s1 = make_float4(0.f, 0.f, 0.f, 0.f);
#pragma unroll
    for (int sp = 0; sp < ASPLIT; sp++) {
        l += g_pl2[(sp * NH + h) * M_TOK + m];
        const float4* p = (const float4*)&g_po[(((size_t)sp * NH + h) * M_TOK + m) * 8];
        float4 x0 = p[0], x1 = p[1];
        s0.x += x0.x; s0.y += x0.y; s0.z += x0.z; s0.w += x0.w;
        s1.x += x1.x; s1.y += x1.y; s1.z += x1.z; s1.w += x1.w;
    }
    float inv = 1.0f / l;
    u32 w0 = cvtpack(s0.y * inv, s0.x * inv);
    u32 w1 = cvtpack(s0.w * inv, s0.z * inv);
    u32 w2 = cvtpack(s1.y * inv, s1.x * inv);
    u32 w3 = cvtpack(s1.w * inv, s1.z * inv);
    *(uint4*)&g_attnb[(size_t)m * DM + h * 8] = make_uint4(w0, w1, w2, w3);
}

// ------------- fused prune + output + row norms (x and rgb) ------------------
__global__ void prune_norms(const float* __restrict__ mask, float* __restrict__ out,
                            const float* __restrict__ rgb) {
    const int rid = blockIdx.x * 8 + (threadIdx.x >> 5);   // 0..8191
    const int lane = threadIdx.x & 31;
    if (rid < M_TOK) {
        float m0 = mask[lane], m1 = mask[lane + 32];
        float a = g_x[rid * DM + lane] * m0;
        float b = g_x[rid * DM + lane + 32] * m1;
        g_x[rid * DM + lane] = a; g_x[rid * DM + lane + 32] = b;
        out[rid * DM + lane] = a; out[rid * DM + lane + 32] = b;
        float sq = a * a + b * b;
#pragma unroll
        for (int o = 16; o; o >>= 1) sq += __shfl_xor_sync(0xffffffffu, sq, o);
        if (lane == 0) g_nx[rid] = sq;
    } else {
        const float* src = rgb + (size_t)(rid - M_TOK) * DM;
        float a = src[lane], b = src[lane + 32];
        float sq = a * a + b * b;
#pragma unroll
        for (int o = 16; o; o >>= 1) sq += __shfl_xor_sync(0xffffffffu, sq, o);
        if (lane == 0) g_ny[rid - M_TOK] = sq;
    }
}

// ---------------- MMD: tf32 tensor-core pairwise Gaussian sums ---------------
__global__ void mmd_kernel(const float* __restrict__ rgb) {
    __shared__ float As[64][68];
    __shared__ float Bs[64][68];
    __shared__ float nA[64], nB[64];
    __shared__ float red[256];
    const int z = blockIdx.z;
    const int bx = blockIdx.x, by = blockIdx.y;
    const int tid = threadIdx.x;
    if (z < 2 && bx < by) {
        if (tid == 0) g_part[z * 4096 + by * 64 + bx] = 0.0f;
        return;
    }
    const float* A = (z == 1) ? rgb : g_x;
    const float* B = (z == 0) ? g_x : rgb;
    const float* nAp = (z == 1) ? g_ny : g_nx;
    const float* nBp = (z == 0) ? g_nx : g_ny;
    const int m0 = by * 64, n0 = bx * 64;
#pragma unroll
    for (int i = 0; i < 4; i++) {
        int fidx = tid + i * 256;
        int rr = fidx >> 4, c4 = fidx & 15;
        float4 va = *(const float4*)&A[(size_t)(m0 + rr) * DM + c4 * 4];
        float4 vb = *(const float4*)&B[(size_t)(n0 + rr) * DM + c4 * 4];
        As[c4 * 4 + 0][rr] = tf32r(va.x); As[c4 * 4 + 1][rr] = tf32r(va.y);
        As[c4 * 4 + 2][rr] = tf32r(va.z); As[c4 * 4 + 3][rr] = tf32r(va.w);
        Bs[c4 * 4 + 0][rr] = tf32r(vb.x); Bs[c4 * 4 + 1][rr] = tf32r(vb.y);
        Bs[c4 * 4 + 2][rr] = tf32r(vb.z); Bs[c4 * 4 + 3][rr] = tf32r(vb.w);
    }
    if (tid < 64) { nA[tid] = nAp[m0 + tid]; nB[tid] = nBp[n0 + tid]; }
    __syncthreads();
    const int w = tid >> 5, lane = tid & 31;
    const int wm = (w >> 1) * 16, wn = (w & 1) * 32;
    const int r = lane >> 2, c = lane & 3;
    float a[8][4];
#pragma unroll
    for (int ks = 0; ks < 8; ks++) {
        a[ks][0] = As[ks * 8 + c][wm + r];
        a[ks][1] = As[ks * 8 + c][wm + r + 8];
        a[ks][2] = As[ks * 8 + c + 4][wm + r];
        a[ks][3] = As[ks * 8 + c + 4][wm + r + 8];
    }
    float acc[4][4] = {};
#pragma unroll
    for (int ks = 0; ks < 8; ks++) {
#pragma unroll
        for (int s = 0; s < 4; s++) {
            float b0 = Bs[ks * 8 + c][wn + s * 8 + r];
            float b1 = Bs[ks * 8 + c + 4][wn + s * 8 + r];
            mma_tf32(acc[s][0], acc[s][1], acc[s][2], acc[s][3],
                     a[ks][0], a[ks][1], a[ks][2], a[ks][3], b0, b1);
        }
    }
    const float c2 = -0.5f * 1.4426950408889634f;
    const float na0 = nA[wm + r], na1 = nA[wm + r + 8];
    float sum = 0.0f;
#pragma unroll
    for (int s = 0; s < 4; s++) {
        float nb0 = nB[wn + s * 8 + 2 * c], nb1 = nB[wn + s * 8 + 2 * c + 1];
        sum += ex2(c2 * (na0 + nb0 - 2.0f * acc[s][0]));
        sum += ex2(c2 * (na0 + nb1 - 2.0f * acc[s][1]));
        sum += ex2(c2 * (na1 + nb0 - 2.0f * acc[s][2]));
        sum += ex2(c2 * (na1 + nb1 - 2.0f * acc[s][3]));
    }
    if (z < 2 && bx != by) sum *= 2.0f;
    red[tid] = sum;
    __syncthreads();
#pragma unroll
    for (int s = 128; s; s >>= 1) {
        if (tid < s) red[tid] += red[tid + s];
        __syncthreads();
    }
    if (tid == 0) g_part[z * 4096 + by * 64 + bx] = red[0];
}

__global__ void mmd_final(float* __restrict__ out) {
    __shared__ float red[256];
    const int tid = threadIdx.x;
    float s[3];
    for (int z = 0; z < 3; z++) {
        float acc = 0.0f;
        for (int i = tid; i < 4096; i += 256) acc += g_part[z * 4096 + i];
        red[tid] = acc;
        __syncthreads();
#pragma unroll
        for (int st = 128; st; st >>= 1) {
            if (tid < st) red[tid] += red[tid + st];
            __syncthreads();
        }
        s[z] = red[0];
        __syncthreads();
    }
    if (tid == 0) {
        const float inv = 1.0f / (4096.0f * 4096.0f);
        out[M_TOK * DM] = (s[0] + s[1] - 2.0f * s[2]) * inv;
    }
}

// ---------------- host orchestration ----------------------------------------
extern "C" void kernel_launch(void* const* d_in, const int* in_sizes, int n_in,
                              void* d_out, int out_size) {
    (void)in_sizes; (void)n_in; (void)out_size;
    const float* hsi  = (const float*)d_in[0];
    const float* rgb  = (const float*)d_in[1];
    const float* ipw  = (const float*)d_in[2];
    const float* ipb  = (const float*)d_in[3];
    const float* ow   = (const float*)d_in[4];
    const float* ob   = (const float*)d_in[5];
    const float* l1w  = (const float*)d_in[6];
    const float* l1b  = (const float*)d_in[7];
    const float* l2w  = (const float*)d_in[8];
    const float* l2b  = (const float*)d_in[9];
    const float* n1w  = (const float*)d_in[10];
    const float* n1b  = (const float*)d_in[11];
    const float* n2w  = (const float*)d_in[12];
    const float* n2b  = (const float*)d_in[13];
    const float* mask = (const float*)d_in[14];
    float* out = (float*)d_out;

    __nv_bfloat16 *pipwb, *powb, *pl1wb, *pl2wb, *pattnb, *pffb;
    cudaGetSymbolAddress((void**)&pipwb, g_ipwb);
    cudaGetSymbolAddress((void**)&powb, g_owb);
    cudaGetSymbolAddress((void**)&pl1wb, g_l1wb);
    cudaGetSymbolAddress((void**)&pl2wb, g_l2wb);
    cudaGetSymbolAddress((void**)&pattnb, g_attnb);
    cudaGetSymbolAddress((void**)&pffb, g_ffb);

    prep_weights<<<768, 256>>>(ipw, ow, l1w, l2w);
    init_kernel<<<1024, 128>>>(hsi);

    for (int l = 0; l < NL; l++) {
        gemm_qkv<<<dim3(3, 64), 256>>>(pipwb + (size_t)l * 192 * 64, ipb + l * 192);
        attn_kernel<<<dim3(M_TOK / 128, NH, ASPLIT), 256>>>();
        attn_combine<<<128, 256>>>();
        gemm_lnb<<<64, 256>>>(pattnb, 64, powb + (size_t)l * 64 * 64, ob + l * 64,
                              n1w + l * 64, n1b + l * 64);
        gemm_ffn1<<<dim3(4, 64), 256>>>(pl1wb + (size_t)l * 256 * 64, l1b + l * 256);
        gemm_lnb<<<64, 256>>>(pffb, 256, pl2wb + (size_t)l * 64 * 256, l2b + l * 64,
                              n2w + l * 64, n2b + l * 64);
    }
    prune_norms<<<1024, 256>>>(mask, out, rgb);
    mmd_kernel<<<dim3(64, 64, 3), 256>>>(rgb);
    mmd_final<<<1, 256>>>(out);
}